// round 1
// baseline (speedup 1.0000x reference)
#include <cuda_runtime.h>
#include <math.h>

#define T 4096
#define D 1024
#define H 16
#define DH 64
#define L 32

#define BM 128
#define BN 64
#define BK 16

// Scratch (allocation-free rule: __device__ globals)
__device__ float g_Qh[H * T * DH];
__device__ float g_Kh[H * T * DH];
__device__ float g_Vh[H * T * DH];
__device__ float g_Vals[T * D];

// ---------------------------------------------------------------------------
// GEMM: out = X[M,K] @ W[N,K]^T.  M=4096, N=1024, K=1024.
// mode 0: plain row-major out [T, 1024]
// mode 1: RoPE epilogue + head-major out [H][T][DH] (BN==DH so bx == head)
// ---------------------------------------------------------------------------
__global__ __launch_bounds__(256) void proj_kernel(
    const float* __restrict__ X, const float* __restrict__ W,
    const float* __restrict__ freqs, float* __restrict__ out, int mode)
{
    __shared__ float As[BK][BM + 2];
    __shared__ float Bs[BK][BN + 2];
    __shared__ float Cs[BM][L + 1];

    const int tid = threadIdx.x;
    const int tx = tid & 15, ty = tid >> 4;
    const int bx = blockIdx.x, by = blockIdx.y;
    const int m0 = ty * 8, n0 = tx * 4;
    const int K = D;

    float acc[8][4];
#pragma unroll
    for (int i = 0; i < 8; i++)
#pragma unroll
        for (int j = 0; j < 4; j++) acc[i][j] = 0.f;

    for (int k0 = 0; k0 < K; k0 += BK) {
        // A tile: 128 rows x 16 k = 512 float4, 2 per thread
#pragma unroll
        for (int it = 0; it < 2; it++) {
            int f = tid + it * 256;
            int row = f >> 2;
            int kv = (f & 3) * 4;
            float4 v4 = *(const float4*)(X + (size_t)(by * BM + row) * K + k0 + kv);
            As[kv + 0][row] = v4.x; As[kv + 1][row] = v4.y;
            As[kv + 2][row] = v4.z; As[kv + 3][row] = v4.w;
        }
        // B tile: 64 rows x 16 k = 256 float4, 1 per thread
        {
            int row = tid >> 2;
            int kv = (tid & 3) * 4;
            float4 v4 = *(const float4*)(W + (size_t)(bx * BN + row) * K + k0 + kv);
            Bs[kv + 0][row] = v4.x; Bs[kv + 1][row] = v4.y;
            Bs[kv + 2][row] = v4.z; Bs[kv + 3][row] = v4.w;
        }
        __syncthreads();

#pragma unroll
        for (int k = 0; k < BK; k++) {
            float a[8], b[4];
#pragma unroll
            for (int i = 0; i < 8; i++) a[i] = As[k][m0 + i];
#pragma unroll
            for (int j = 0; j < 4; j++) b[j] = Bs[k][n0 + j];
#pragma unroll
            for (int i = 0; i < 8; i++)
#pragma unroll
                for (int j = 0; j < 4; j++) acc[i][j] += a[i] * b[j];
        }
        __syncthreads();
    }

    if (mode == 0) {
#pragma unroll
        for (int i = 0; i < 8; i++) {
            int t = by * BM + m0 + i;
#pragma unroll
            for (int j = 0; j < 4; j++)
                out[(size_t)t * D + bx * BN + n0 + j] = acc[i][j];
        }
    } else {
        // RoPE + head-major write. h = bx, d = n.
        const int h = bx;
#pragma unroll
        for (int i = 0; i < 8; i++) {
            int t = by * BM + m0 + i;
#pragma unroll
            for (int j = 0; j < 4; j++) {
                int n = n0 + j;
                if (n >= L) {
                    out[(size_t)h * T * DH + (size_t)t * DH + n] = acc[i][j];
                } else {
                    Cs[m0 + i][n] = acc[i][j];
                }
            }
        }
        __syncthreads();
        if (n0 < L) {
#pragma unroll
            for (int i = 0; i < 8; i++) {
                int t = by * BM + m0 + i;
#pragma unroll
                for (int j = 0; j < 4; j++) {
                    int l = n0 + j;
                    float x = Cs[m0 + i][l];
                    float p = Cs[m0 + i][l ^ 16];
                    float r = (l < 16) ? -p : p;
                    float f = freqs[(size_t)t * L + l];
                    out[(size_t)h * T * DH + (size_t)t * DH + l] =
                        x * cosf(f) + r * sinf(f);
                }
            }
        }
    }
}

// ---------------------------------------------------------------------------
// Causal flash attention, fp32. One block = (head, 64-query tile).
// 256 threads as 16x16, 4x4 thread tiles.
// ---------------------------------------------------------------------------
__global__ __launch_bounds__(256) void attn_kernel(
    const float* __restrict__ Q, const float* __restrict__ Kg,
    const float* __restrict__ Vg, float* __restrict__ vals)
{
    extern __shared__ float sm[];
    float (*Qs)[65] = (float(*)[65])sm;
    float (*Ks)[65] = (float(*)[65])(sm + 64 * 65);
    float (*Vs)[65] = (float(*)[65])(sm + 2 * 64 * 65);
    float (*Ps)[65] = (float(*)[65])(sm + 3 * 64 * 65);

    const int tid = threadIdx.x;
    const int tx = tid & 15, ty = tid >> 4;
    const int qb = blockIdx.x, h = blockIdx.y;

    const float* Qh = Q + (size_t)h * T * DH;
    const float* Kh = Kg + (size_t)h * T * DH;
    const float* Vh = Vg + (size_t)h * T * DH;

    // load Q tile: 64 rows x 64 dims = 1024 float4, 4 per thread
#pragma unroll
    for (int it = 0; it < 4; it++) {
        int f = tid + it * 256;
        int r = f >> 4;
        int d4 = (f & 15) * 4;
        float4 v4 = *(const float4*)(Qh + (size_t)(qb * 64 + r) * DH + d4);
        Qs[r][d4 + 0] = v4.x; Qs[r][d4 + 1] = v4.y;
        Qs[r][d4 + 2] = v4.z; Qs[r][d4 + 3] = v4.w;
    }

    float o[4][4];
    float mrow[4], lrow[4];
#pragma unroll
    for (int i = 0; i < 4; i++) {
        mrow[i] = -1e30f; lrow[i] = 0.f;
#pragma unroll
        for (int j = 0; j < 4; j++) o[i][j] = 0.f;
    }
    const float scale = 0.125f;  // 1/sqrt(64)

    for (int jb = 0; jb <= qb; jb++) {
        __syncthreads();  // previous iter's Ks/Vs/Ps reads done (also Qs load on first)
#pragma unroll
        for (int it = 0; it < 4; it++) {
            int f = tid + it * 256;
            int r = f >> 4;
            int d4 = (f & 15) * 4;
            float4 kv = *(const float4*)(Kh + (size_t)(jb * 64 + r) * DH + d4);
            Ks[r][d4 + 0] = kv.x; Ks[r][d4 + 1] = kv.y;
            Ks[r][d4 + 2] = kv.z; Ks[r][d4 + 3] = kv.w;
            float4 vv = *(const float4*)(Vh + (size_t)(jb * 64 + r) * DH + d4);
            Vs[r][d4 + 0] = vv.x; Vs[r][d4 + 1] = vv.y;
            Vs[r][d4 + 2] = vv.z; Vs[r][d4 + 3] = vv.w;
        }
        __syncthreads();

        // S = Q K^T (4x4 per thread)
        float s[4][4];
#pragma unroll
        for (int i = 0; i < 4; i++)
#pragma unroll
            for (int j = 0; j < 4; j++) s[i][j] = 0.f;
#pragma unroll
        for (int k = 0; k < 64; k++) {
            float qf[4], kf[4];
#pragma unroll
            for (int i = 0; i < 4; i++) qf[i] = Qs[ty * 4 + i][k];
#pragma unroll
            for (int j = 0; j < 4; j++) kf[j] = Ks[tx * 4 + j][k];
#pragma unroll
            for (int i = 0; i < 4; i++)
#pragma unroll
                for (int j = 0; j < 4; j++) s[i][j] += qf[i] * kf[j];
        }
#pragma unroll
        for (int i = 0; i < 4; i++)
#pragma unroll
            for (int j = 0; j < 4; j++) {
                s[i][j] *= scale;
                if (jb == qb && (tx * 4 + j) > (ty * 4 + i)) s[i][j] = -1e30f;
            }

        // online softmax update
#pragma unroll
        for (int i = 0; i < 4; i++) {
            float mx = s[i][0];
#pragma unroll
            for (int j = 1; j < 4; j++) mx = fmaxf(mx, s[i][j]);
#pragma unroll
            for (int msk = 1; msk <= 8; msk <<= 1)
                mx = fmaxf(mx, __shfl_xor_sync(0xffffffffu, mx, msk));
            float mnew = fmaxf(mrow[i], mx);
            float alpha = expf(mrow[i] - mnew);
            mrow[i] = mnew;
            float rsum = 0.f;
#pragma unroll
            for (int j = 0; j < 4; j++) {
                float p = expf(s[i][j] - mnew);
                Ps[ty * 4 + i][tx * 4 + j] = p;
                rsum += p;
            }
#pragma unroll
            for (int msk = 1; msk <= 8; msk <<= 1)
                rsum += __shfl_xor_sync(0xffffffffu, rsum, msk);
            lrow[i] = lrow[i] * alpha + rsum;
#pragma unroll
            for (int j = 0; j < 4; j++) o[i][j] *= alpha;
        }
        __syncthreads();  // Ps fully written

        // O += P V
#pragma unroll
        for (int jj = 0; jj < 64; jj++) {
            float pf[4], vf[4];
#pragma unroll
            for (int i = 0; i < 4; i++) pf[i] = Ps[ty * 4 + i][jj];
#pragma unroll
            for (int j = 0; j < 4; j++) vf[j] = Vs[jj][tx * 4 + j];
#pragma unroll
            for (int i = 0; i < 4; i++)
#pragma unroll
                for (int j = 0; j < 4; j++) o[i][j] += pf[i] * vf[j];
        }
    }

#pragma unroll
    for (int i = 0; i < 4; i++) {
        int t = qb * 64 + ty * 4 + i;
        float inv = 1.f / lrow[i];
#pragma unroll
        for (int j = 0; j < 4; j++)
            vals[(size_t)t * D + h * DH + tx * 4 + j] = o[i][j] * inv;
    }
}

// ---------------------------------------------------------------------------
extern "C" void kernel_launch(void* const* d_in, const int* in_sizes, int n_in,
                              void* d_out, int out_size)
{
    const float* q     = (const float*)d_in[0];
    const float* k     = (const float*)d_in[1];
    const float* v     = (const float*)d_in[2];
    // d_in[3] = mask (causal tril, known statically — unused)
    const float* freqs = (const float*)d_in[4];
    const float* w_q   = (const float*)d_in[5];
    const float* w_k   = (const float*)d_in[6];
    const float* w_v   = (const float*)d_in[7];
    const float* w_o   = (const float*)d_in[8];
    float* out = (float*)d_out;

    float *Qh, *Kh, *Vh, *Vals;
    cudaGetSymbolAddress((void**)&Qh, g_Qh);
    cudaGetSymbolAddress((void**)&Kh, g_Kh);
    cudaGetSymbolAddress((void**)&Vh, g_Vh);
    cudaGetSymbolAddress((void**)&Vals, g_Vals);

    dim3 pgrid(D / BN, T / BM);  // (16, 32)
    proj_kernel<<<pgrid, 256>>>(q, w_q, freqs, Qh, 1);
    proj_kernel<<<pgrid, 256>>>(k, w_k, freqs, Kh, 1);
    proj_kernel<<<pgrid, 256>>>(v, w_v, freqs, Vh, 1);

    size_t smem = 4 * 64 * 65 * sizeof(float);  // 66560 B
    cudaFuncSetAttribute(attn_kernel,
                         cudaFuncAttributeMaxDynamicSharedMemorySize, (int)smem);
    attn_kernel<<<dim3(T / 64, H), 256, smem>>>(Qh, Kh, Vh, Vals);

    proj_kernel<<<pgrid, 256>>>(Vals, w_o, nullptr, out, 0);
}

// round 2
// speedup vs baseline: 2.9285x; 2.9285x over previous
#include <cuda_runtime.h>
#include <math.h>
#include <stdint.h>

#define T 4096
#define D 1024
#define H 16
#define DH 64
#define L 32

// Scratch (allocation-free rule: __device__ globals)
__device__ float g_Qh[H * T * DH];
__device__ float g_Kh[H * T * DH];
__device__ float g_Vh[H * T * DH];
__device__ float g_Vals[T * D];

__device__ __forceinline__ uint32_t f2tf(float f) {
    uint32_t r;
    asm("cvt.rna.tf32.f32 %0, %1;" : "=r"(r) : "f"(f));
    return r;
}

__device__ __forceinline__ void mma_tf32(float c[4], uint32_t a0, uint32_t a1,
                                         uint32_t a2, uint32_t a3,
                                         uint32_t b0, uint32_t b1) {
    asm volatile(
        "mma.sync.aligned.m16n8k8.row.col.f32.tf32.tf32.f32 "
        "{%0,%1,%2,%3}, {%4,%5,%6,%7}, {%8,%9}, {%0,%1,%2,%3};\n"
        : "+f"(c[0]), "+f"(c[1]), "+f"(c[2]), "+f"(c[3])
        : "r"(a0), "r"(a1), "r"(a2), "r"(a3), "r"(b0), "r"(b1));
}

// ---------------------------------------------------------------------------
// Projection GEMM on tensor cores (tf32).
// out = X[M,K] @ W[N,K]^T.  M=4096, N=1024, K=1024.
// Block tile 128x64, BK=32. 256 threads = 8 warps (4 M x 2 N), warp tile 32x32.
// mode 0: plain row-major out [T,1024].
// mode 1: RoPE epilogue + head-major out [H][T][DH] (BN==DH so bx == head).
// ---------------------------------------------------------------------------
__global__ __launch_bounds__(256) void proj_kernel(
    const float* __restrict__ X, const float* __restrict__ W,
    const float* __restrict__ freqs, float* __restrict__ out, int mode)
{
    __shared__ uint32_t As[128 * 32];
    __shared__ uint32_t Bs[64 * 32];

    const int tid = threadIdx.x;
    const int lane = tid & 31;
    const int w = tid >> 5;
    const int gid = lane >> 2;   // 0..7
    const int tig = lane & 3;    // 0..3
    const int wm = w >> 1;       // 0..3
    const int wn = w & 1;        // 0..1
    const int bx = blockIdx.x, by = blockIdx.y;

    float acc[2][4][4];
#pragma unroll
    for (int mt = 0; mt < 2; mt++)
#pragma unroll
        for (int nt = 0; nt < 4; nt++)
#pragma unroll
            for (int r = 0; r < 4; r++) acc[mt][nt][r] = 0.f;

    // gmem load indices (A: 4 float4/thread, B: 2 float4/thread)
    int am[4], akg[4], bm[2], bkg[2];
#pragma unroll
    for (int i = 0; i < 4; i++) {
        int f = tid + i * 256;
        am[i] = f >> 3;
        akg[i] = f & 7;
    }
#pragma unroll
    for (int i = 0; i < 2; i++) {
        int f = tid + i * 256;
        bm[i] = f >> 3;
        bkg[i] = f & 7;
    }

    float4 ra[4], rb[2];
#pragma unroll
    for (int i = 0; i < 4; i++)
        ra[i] = *(const float4*)(X + (size_t)(by * 128 + am[i]) * D + akg[i] * 4);
#pragma unroll
    for (int i = 0; i < 2; i++)
        rb[i] = *(const float4*)(W + (size_t)(bx * 64 + bm[i]) * D + bkg[i] * 4);

    for (int kk = 0; kk < 32; kk++) {
        __syncthreads();
        // STS with tf32 conversion, XOR swizzle on k-group
#pragma unroll
        for (int i = 0; i < 4; i++) {
            uint4 u = make_uint4(f2tf(ra[i].x), f2tf(ra[i].y), f2tf(ra[i].z), f2tf(ra[i].w));
            *(uint4*)&As[am[i] * 32 + ((akg[i] ^ (am[i] & 7)) << 2)] = u;
        }
#pragma unroll
        for (int i = 0; i < 2; i++) {
            uint4 u = make_uint4(f2tf(rb[i].x), f2tf(rb[i].y), f2tf(rb[i].z), f2tf(rb[i].w));
            *(uint4*)&Bs[bm[i] * 32 + ((bkg[i] ^ (bm[i] & 7)) << 2)] = u;
        }
        __syncthreads();

        if (kk < 31) {
            int k0 = (kk + 1) * 32;
#pragma unroll
            for (int i = 0; i < 4; i++)
                ra[i] = *(const float4*)(X + (size_t)(by * 128 + am[i]) * D + k0 + akg[i] * 4);
#pragma unroll
            for (int i = 0; i < 2; i++)
                rb[i] = *(const float4*)(W + (size_t)(bx * 64 + bm[i]) * D + k0 + bkg[i] * 4);
        }

#pragma unroll
        for (int ks = 0; ks < 4; ks++) {
            int kb = ks * 8;
            uint32_t a[2][4];
#pragma unroll
            for (int mt = 0; mt < 2; mt++) {
                int m0 = wm * 32 + mt * 16;
                int r0 = m0 + gid, r1 = m0 + gid + 8;
                a[mt][0] = As[r0 * 32 + ((kb + tig) ^ ((r0 & 7) << 2))];
                a[mt][1] = As[r1 * 32 + ((kb + tig) ^ ((r1 & 7) << 2))];
                a[mt][2] = As[r0 * 32 + ((kb + tig + 4) ^ ((r0 & 7) << 2))];
                a[mt][3] = As[r1 * 32 + ((kb + tig + 4) ^ ((r1 & 7) << 2))];
            }
#pragma unroll
            for (int nt = 0; nt < 4; nt++) {
                int n0 = wn * 32 + nt * 8 + gid;
                uint32_t b0 = Bs[n0 * 32 + ((kb + tig) ^ ((n0 & 7) << 2))];
                uint32_t b1 = Bs[n0 * 32 + ((kb + tig + 4) ^ ((n0 & 7) << 2))];
#pragma unroll
                for (int mt = 0; mt < 2; mt++)
                    mma_tf32(acc[mt][nt], a[mt][0], a[mt][1], a[mt][2], a[mt][3], b0, b1);
            }
        }
    }

    // Epilogue
    if (mode == 0) {
#pragma unroll
        for (int mt = 0; mt < 2; mt++) {
#pragma unroll
            for (int rh = 0; rh < 2; rh++) {
                int t = by * 128 + wm * 32 + mt * 16 + gid + rh * 8;
#pragma unroll
                for (int nt = 0; nt < 4; nt++) {
                    int col = bx * 64 + wn * 32 + nt * 8 + tig * 2;
                    float2 v = make_float2(acc[mt][nt][rh * 2], acc[mt][nt][rh * 2 + 1]);
                    *(float2*)(out + (size_t)t * D + col) = v;
                }
            }
        }
    } else {
        const int h = bx;
        if (wn == 0) {
            // cols 0..31: RoPE in registers (partner nt^2 lives in same thread)
#pragma unroll
            for (int mt = 0; mt < 2; mt++) {
#pragma unroll
                for (int rh = 0; rh < 2; rh++) {
                    int t = by * 128 + wm * 32 + mt * 16 + gid + rh * 8;
#pragma unroll
                    for (int nt = 0; nt < 4; nt++) {
                        int l = nt * 8 + tig * 2;
                        float2 f2 = *(const float2*)(freqs + (size_t)t * L + l);
                        float x0 = acc[mt][nt][rh * 2];
                        float x1 = acc[mt][nt][rh * 2 + 1];
                        float p0 = acc[mt][nt ^ 2][rh * 2];
                        float p1 = acc[mt][nt ^ 2][rh * 2 + 1];
                        float r0 = (nt < 2) ? -p0 : p0;
                        float r1 = (nt < 2) ? -p1 : p1;
                        float2 v;
                        v.x = x0 * __cosf(f2.x) + r0 * __sinf(f2.x);
                        v.y = x1 * __cosf(f2.y) + r1 * __sinf(f2.y);
                        *(float2*)(out + (size_t)h * T * DH + (size_t)t * DH + l) = v;
                    }
                }
            }
        } else {
            // cols 32..63: passthrough
#pragma unroll
            for (int mt = 0; mt < 2; mt++) {
#pragma unroll
                for (int rh = 0; rh < 2; rh++) {
                    int t = by * 128 + wm * 32 + mt * 16 + gid + rh * 8;
#pragma unroll
                    for (int nt = 0; nt < 4; nt++) {
                        int col = 32 + nt * 8 + tig * 2;
                        float2 v = make_float2(acc[mt][nt][rh * 2], acc[mt][nt][rh * 2 + 1]);
                        *(float2*)(out + (size_t)h * T * DH + (size_t)t * DH + col) = v;
                    }
                }
            }
        }
    }
}

// ---------------------------------------------------------------------------
// Causal flash attention, tf32 tensor cores.
// Block = (head, 64-query tile), 128 threads = 4 warps, each warp 16 q-rows.
// ---------------------------------------------------------------------------
__global__ __launch_bounds__(128) void attn_kernel(
    const float* __restrict__ Q, const float* __restrict__ Kg,
    const float* __restrict__ Vg, float* __restrict__ vals)
{
    extern __shared__ uint32_t sm[];
    uint32_t* Qs = sm;            // 64x64
    uint32_t* Ks = sm + 4096;
    uint32_t* Vs = sm + 8192;
    uint32_t* Ps = sm + 12288;

    const int tid = threadIdx.x;
    const int lane = tid & 31;
    const int w = tid >> 5;
    const int gid = lane >> 2;
    const int tig = lane & 3;
    const int qb = 63 - blockIdx.x;   // long tiles first
    const int h = blockIdx.y;

    const float* Qh = Q + (size_t)h * T * DH;
    const float* Kh = Kg + (size_t)h * T * DH;
    const float* Vh = Vg + (size_t)h * T * DH;

    // Load Q tile, pre-scaled by 1/sqrt(DH)=0.125, tf32, swizzled
#pragma unroll
    for (int i = 0; i < 8; i++) {
        int f = tid + i * 128;
        int m = f >> 4, kg = f & 15;
        float4 v4 = *(const float4*)(Qh + (size_t)(qb * 64 + m) * DH + kg * 4);
        uint4 u = make_uint4(f2tf(v4.x * 0.125f), f2tf(v4.y * 0.125f),
                             f2tf(v4.z * 0.125f), f2tf(v4.w * 0.125f));
        *(uint4*)&Qs[m * 64 + ((kg ^ (m & 7)) << 2)] = u;
    }

    float o[8][4];
#pragma unroll
    for (int nt = 0; nt < 8; nt++)
#pragma unroll
        for (int r = 0; r < 4; r++) o[nt][r] = 0.f;
    float mr[2] = {-1e30f, -1e30f};
    float lr[2] = {0.f, 0.f};

    const int r0 = w * 16 + gid;   // local q-row (first of pair)

    for (int jb = 0; jb <= qb; jb++) {
        __syncthreads();
#pragma unroll
        for (int i = 0; i < 8; i++) {
            int f = tid + i * 128;
            int m = f >> 4, kg = f & 15;
            float4 k4 = *(const float4*)(Kh + (size_t)(jb * 64 + m) * DH + kg * 4);
            uint4 uk = make_uint4(f2tf(k4.x), f2tf(k4.y), f2tf(k4.z), f2tf(k4.w));
            *(uint4*)&Ks[m * 64 + ((kg ^ (m & 7)) << 2)] = uk;
            float4 v4 = *(const float4*)(Vh + (size_t)(jb * 64 + m) * DH + kg * 4);
            uint4 uv = make_uint4(f2tf(v4.x), f2tf(v4.y), f2tf(v4.z), f2tf(v4.w));
            *(uint4*)&Vs[m * 64 + ((kg ^ (m & 7)) << 2)] = uv;
        }
        __syncthreads();

        // S = Q K^T  (16 x 64 per warp)
        float s[8][4];
#pragma unroll
        for (int nt = 0; nt < 8; nt++)
#pragma unroll
            for (int r = 0; r < 4; r++) s[nt][r] = 0.f;

#pragma unroll
        for (int ks = 0; ks < 8; ks++) {
            int kb = ks * 8;
            int ra_ = r0, rb_ = r0 + 8;
            uint32_t a0 = Qs[ra_ * 64 + ((kb + tig) ^ ((ra_ & 7) << 2))];
            uint32_t a1 = Qs[rb_ * 64 + ((kb + tig) ^ ((rb_ & 7) << 2))];
            uint32_t a2 = Qs[ra_ * 64 + ((kb + tig + 4) ^ ((ra_ & 7) << 2))];
            uint32_t a3 = Qs[rb_ * 64 + ((kb + tig + 4) ^ ((rb_ & 7) << 2))];
#pragma unroll
            for (int nt = 0; nt < 8; nt++) {
                int n0 = nt * 8 + gid;
                uint32_t b0 = Ks[n0 * 64 + ((kb + tig) ^ ((n0 & 7) << 2))];
                uint32_t b1 = Ks[n0 * 64 + ((kb + tig + 4) ^ ((n0 & 7) << 2))];
                mma_tf32(s[nt], a0, a1, a2, a3, b0, b1);
            }
        }

        // causal mask on diagonal tile
        if (jb == qb) {
#pragma unroll
            for (int nt = 0; nt < 8; nt++)
#pragma unroll
                for (int r = 0; r < 4; r++) {
                    int col = nt * 8 + tig * 2 + (r & 1);
                    int row = w * 16 + gid + ((r & 2) ? 8 : 0);
                    if (col > row) s[nt][r] = -1e30f;
                }
        }

        // online softmax (two rows per thread)
#pragma unroll
        for (int half = 0; half < 2; half++) {
            float mx = -1e30f;
#pragma unroll
            for (int nt = 0; nt < 8; nt++) {
                mx = fmaxf(mx, s[nt][half * 2]);
                mx = fmaxf(mx, s[nt][half * 2 + 1]);
            }
            mx = fmaxf(mx, __shfl_xor_sync(0xffffffffu, mx, 1));
            mx = fmaxf(mx, __shfl_xor_sync(0xffffffffu, mx, 2));
            float mnew = fmaxf(mr[half], mx);
            float alpha = __expf(mr[half] - mnew);
            mr[half] = mnew;
            float rs = 0.f;
#pragma unroll
            for (int nt = 0; nt < 8; nt++) {
                float p0 = __expf(s[nt][half * 2] - mnew);
                float p1 = __expf(s[nt][half * 2 + 1] - mnew);
                s[nt][half * 2] = p0;
                s[nt][half * 2 + 1] = p1;
                rs += p0 + p1;
            }
            rs += __shfl_xor_sync(0xffffffffu, rs, 1);
            rs += __shfl_xor_sync(0xffffffffu, rs, 2);
            lr[half] = lr[half] * alpha + rs;
#pragma unroll
            for (int nt = 0; nt < 8; nt++) {
                o[nt][half * 2] *= alpha;
                o[nt][half * 2 + 1] *= alpha;
            }
        }

        // write P (tf32) to warp-private smem rows
#pragma unroll
        for (int nt = 0; nt < 8; nt++) {
            int col = nt * 8 + tig * 2;
            int ra_ = r0, rb_ = r0 + 8;
            uint2 p01 = make_uint2(f2tf(s[nt][0]), f2tf(s[nt][1]));
            *(uint2*)&Ps[ra_ * 64 + (col ^ ((ra_ & 7) << 2))] = p01;
            uint2 p23 = make_uint2(f2tf(s[nt][2]), f2tf(s[nt][3]));
            *(uint2*)&Ps[rb_ * 64 + (col ^ ((rb_ & 7) << 2))] = p23;
        }
        __syncwarp();

        // O += P V
#pragma unroll
        for (int ks = 0; ks < 8; ks++) {
            int kb = ks * 8;
            int ra_ = r0, rb_ = r0 + 8;
            uint32_t a0 = Ps[ra_ * 64 + ((kb + tig) ^ ((ra_ & 7) << 2))];
            uint32_t a1 = Ps[rb_ * 64 + ((kb + tig) ^ ((rb_ & 7) << 2))];
            uint32_t a2 = Ps[ra_ * 64 + ((kb + tig + 4) ^ ((ra_ & 7) << 2))];
            uint32_t a3 = Ps[rb_ * 64 + ((kb + tig + 4) ^ ((rb_ & 7) << 2))];
#pragma unroll
            for (int nt = 0; nt < 8; nt++) {
                int kr0 = kb + tig, kr1 = kb + tig + 4;
                uint32_t b0 = Vs[kr0 * 64 + ((nt * 8 + gid) ^ ((kr0 & 7) << 2))];
                uint32_t b1 = Vs[kr1 * 64 + ((nt * 8 + gid) ^ ((kr1 & 7) << 2))];
                mma_tf32(o[nt], a0, a1, a2, a3, b0, b1);
            }
        }
    }

    // epilogue: normalize and store
    float inv0 = 1.f / lr[0];
    float inv1 = 1.f / lr[1];
    int t0 = qb * 64 + r0;
    int t1 = t0 + 8;
#pragma unroll
    for (int nt = 0; nt < 8; nt++) {
        int col = h * DH + nt * 8 + tig * 2;
        float2 v0 = make_float2(o[nt][0] * inv0, o[nt][1] * inv0);
        *(float2*)(vals + (size_t)t0 * D + col) = v0;
        float2 v1 = make_float2(o[nt][2] * inv1, o[nt][3] * inv1);
        *(float2*)(vals + (size_t)t1 * D + col) = v1;
    }
}

// ---------------------------------------------------------------------------
extern "C" void kernel_launch(void* const* d_in, const int* in_sizes, int n_in,
                              void* d_out, int out_size)
{
    const float* q     = (const float*)d_in[0];
    const float* k     = (const float*)d_in[1];
    const float* v     = (const float*)d_in[2];
    // d_in[3] = mask (causal tril, known statically — unused)
    const float* freqs = (const float*)d_in[4];
    const float* w_q   = (const float*)d_in[5];
    const float* w_k   = (const float*)d_in[6];
    const float* w_v   = (const float*)d_in[7];
    const float* w_o   = (const float*)d_in[8];
    float* out = (float*)d_out;

    float *Qh, *Kh, *Vh, *Vals;
    cudaGetSymbolAddress((void**)&Qh, g_Qh);
    cudaGetSymbolAddress((void**)&Kh, g_Kh);
    cudaGetSymbolAddress((void**)&Vh, g_Vh);
    cudaGetSymbolAddress((void**)&Vals, g_Vals);

    dim3 pgrid(D / 64, T / 128);  // (16, 32)
    proj_kernel<<<pgrid, 256>>>(q, w_q, freqs, Qh, 1);
    proj_kernel<<<pgrid, 256>>>(k, w_k, freqs, Kh, 1);
    proj_kernel<<<pgrid, 256>>>(v, w_v, freqs, Vh, 1);

    size_t smem = 4 * 64 * 64 * sizeof(uint32_t);  // 64 KB
    static int attr_set = 0;
    cudaFuncSetAttribute(attn_kernel,
                         cudaFuncAttributeMaxDynamicSharedMemorySize, (int)smem);
    (void)attr_set;
    attn_kernel<<<dim3(T / 64, H), 128, smem>>>(Qh, Kh, Vh, Vals);

    proj_kernel<<<pgrid, 256>>>(Vals, w_o, nullptr, out, 0);
}

// round 3
// speedup vs baseline: 3.1068x; 1.0609x over previous
#include <cuda_runtime.h>
#include <math.h>
#include <stdint.h>

#define T 4096
#define D 1024
#define H 16
#define DH 64
#define L 32

// Scratch (allocation-free rule: __device__ globals)
__device__ float g_Qh[H * T * DH];
__device__ float g_Kh[H * T * DH];
__device__ float g_Vh[H * T * DH];
__device__ float g_Vals[T * D];

__device__ __forceinline__ uint32_t f2tf(float f) {
    uint32_t r;
    asm("cvt.rna.tf32.f32 %0, %1;" : "=r"(r) : "f"(f));
    return r;
}

__device__ __forceinline__ void mma_tf32(float c[4], uint32_t a0, uint32_t a1,
                                         uint32_t a2, uint32_t a3,
                                         uint32_t b0, uint32_t b1) {
    asm volatile(
        "mma.sync.aligned.m16n8k8.row.col.f32.tf32.tf32.f32 "
        "{%0,%1,%2,%3}, {%4,%5,%6,%7}, {%8,%9}, {%0,%1,%2,%3};\n"
        : "+f"(c[0]), "+f"(c[1]), "+f"(c[2]), "+f"(c[3])
        : "r"(a0), "r"(a1), "r"(a2), "r"(a3), "r"(b0), "r"(b1));
}

__device__ __forceinline__ void ldsm4(uint32_t& d0, uint32_t& d1, uint32_t& d2,
                                      uint32_t& d3, uint32_t saddr) {
    asm volatile(
        "ldmatrix.sync.aligned.m8n8.x4.shared.b16 {%0,%1,%2,%3}, [%4];"
        : "=r"(d0), "=r"(d1), "=r"(d2), "=r"(d3)
        : "r"(saddr));
}

// ---------------------------------------------------------------------------
// Projection GEMM on tensor cores (tf32) with ldmatrix fragment loads.
// out = X[M,K] @ W[N,K]^T.  M=4096, N=1024, K=1024.
// Block tile 128x64, BK=32. 256 threads = 8 warps (4 M x 2 N), warp tile 32x32.
// mode 0: plain row-major out [T,1024].
// mode 1: RoPE epilogue + head-major out [H][T][DH] (BN==DH so bx == head).
// ---------------------------------------------------------------------------
__global__ __launch_bounds__(256) void proj_kernel(
    const float* __restrict__ X, const float* __restrict__ W,
    const float* __restrict__ freqs, float* __restrict__ out, int mode)
{
    __shared__ uint32_t As[128 * 32];
    __shared__ uint32_t Bs[64 * 32];

    const int tid = threadIdx.x;
    const int lane = tid & 31;
    const int w = tid >> 5;
    const int gid = lane >> 2;   // 0..7
    const int tig = lane & 3;    // 0..3
    const int wm = w >> 1;       // 0..3
    const int wn = w & 1;        // 0..1
    const int bx = blockIdx.x, by = blockIdx.y;

    // ldmatrix per-thread constants
    const int lsub = lane >> 3;          // submatrix id 0..3
    const int lr = lane & 7;             // row within submatrix
    const int khA = lsub >> 1;           // A: k-half select
    const int khB = lsub & 1;            // B: k-half select

    const uint32_t as_s = (uint32_t)__cvta_generic_to_shared(As);
    const uint32_t bs_s = (uint32_t)__cvta_generic_to_shared(Bs);

    // A fragment row (per mt), row stride = 32 words = 128B
    uint32_t aA[2];
#pragma unroll
    for (int mt = 0; mt < 2; mt++) {
        int rowA = wm * 32 + mt * 16 + lr + ((lsub & 1) << 3);
        aA[mt] = as_s + rowA * 128;
    }
    // B fragment row (per nt-pair np)
    uint32_t bB[2];
#pragma unroll
    for (int np = 0; np < 2; np++) {
        int n = wn * 32 + np * 16 + lr + ((lsub >> 1) << 3);
        bB[np] = bs_s + n * 128;
    }

    float acc[2][4][4];
#pragma unroll
    for (int mt = 0; mt < 2; mt++)
#pragma unroll
        for (int nt = 0; nt < 4; nt++)
#pragma unroll
            for (int r = 0; r < 4; r++) acc[mt][nt][r] = 0.f;

    // gmem load indices (A: 4 float4/thread, B: 2 float4/thread)
    int am[4], akg[4], bm[2], bkg[2];
#pragma unroll
    for (int i = 0; i < 4; i++) {
        int f = tid + i * 256;
        am[i] = f >> 3;
        akg[i] = f & 7;
    }
#pragma unroll
    for (int i = 0; i < 2; i++) {
        int f = tid + i * 256;
        bm[i] = f >> 3;
        bkg[i] = f & 7;
    }

    float4 ra[4], rb[2];
#pragma unroll
    for (int i = 0; i < 4; i++)
        ra[i] = *(const float4*)(X + (size_t)(by * 128 + am[i]) * D + akg[i] * 4);
#pragma unroll
    for (int i = 0; i < 2; i++)
        rb[i] = *(const float4*)(W + (size_t)(bx * 64 + bm[i]) * D + bkg[i] * 4);

    for (int kk = 0; kk < 32; kk++) {
        __syncthreads();
        // STS with tf32 conversion, XOR swizzle on k-group
#pragma unroll
        for (int i = 0; i < 4; i++) {
            uint4 u = make_uint4(f2tf(ra[i].x), f2tf(ra[i].y), f2tf(ra[i].z), f2tf(ra[i].w));
            *(uint4*)&As[am[i] * 32 + ((akg[i] ^ (am[i] & 7)) << 2)] = u;
        }
#pragma unroll
        for (int i = 0; i < 2; i++) {
            uint4 u = make_uint4(f2tf(rb[i].x), f2tf(rb[i].y), f2tf(rb[i].z), f2tf(rb[i].w));
            *(uint4*)&Bs[bm[i] * 32 + ((bkg[i] ^ (bm[i] & 7)) << 2)] = u;
        }
        __syncthreads();

        if (kk < 31) {
            int k0 = (kk + 1) * 32;
#pragma unroll
            for (int i = 0; i < 4; i++)
                ra[i] = *(const float4*)(X + (size_t)(by * 128 + am[i]) * D + k0 + akg[i] * 4);
#pragma unroll
            for (int i = 0; i < 2; i++)
                rb[i] = *(const float4*)(W + (size_t)(bx * 64 + bm[i]) * D + k0 + bkg[i] * 4);
        }

#pragma unroll
        for (int ks = 0; ks < 4; ks++) {
            uint32_t a[2][4];
#pragma unroll
            for (int mt = 0; mt < 2; mt++)
                ldsm4(a[mt][0], a[mt][1], a[mt][2], a[mt][3],
                      aA[mt] + (((2 * ks + khA) ^ lr) << 4));
#pragma unroll
            for (int np = 0; np < 2; np++) {
                uint32_t b00, b01, b10, b11;
                ldsm4(b00, b01, b10, b11, bB[np] + (((2 * ks + khB) ^ lr) << 4));
#pragma unroll
                for (int mt = 0; mt < 2; mt++) {
                    mma_tf32(acc[mt][2 * np], a[mt][0], a[mt][1], a[mt][2], a[mt][3], b00, b01);
                    mma_tf32(acc[mt][2 * np + 1], a[mt][0], a[mt][1], a[mt][2], a[mt][3], b10, b11);
                }
            }
        }
    }

    // Epilogue
    if (mode == 0) {
#pragma unroll
        for (int mt = 0; mt < 2; mt++) {
#pragma unroll
            for (int rh = 0; rh < 2; rh++) {
                int t = by * 128 + wm * 32 + mt * 16 + gid + rh * 8;
#pragma unroll
                for (int nt = 0; nt < 4; nt++) {
                    int col = bx * 64 + wn * 32 + nt * 8 + tig * 2;
                    float2 v = make_float2(acc[mt][nt][rh * 2], acc[mt][nt][rh * 2 + 1]);
                    *(float2*)(out + (size_t)t * D + col) = v;
                }
            }
        }
    } else {
        const int h = bx;
        if (wn == 0) {
            // cols 0..31: RoPE in registers (partner nt^2 lives in same thread)
#pragma unroll
            for (int mt = 0; mt < 2; mt++) {
#pragma unroll
                for (int rh = 0; rh < 2; rh++) {
                    int t = by * 128 + wm * 32 + mt * 16 + gid + rh * 8;
#pragma unroll
                    for (int nt = 0; nt < 4; nt++) {
                        int l = nt * 8 + tig * 2;
                        float2 f2 = *(const float2*)(freqs + (size_t)t * L + l);
                        float x0 = acc[mt][nt][rh * 2];
                        float x1 = acc[mt][nt][rh * 2 + 1];
                        float p0 = acc[mt][nt ^ 2][rh * 2];
                        float p1 = acc[mt][nt ^ 2][rh * 2 + 1];
                        float r0 = (nt < 2) ? -p0 : p0;
                        float r1 = (nt < 2) ? -p1 : p1;
                        float2 v;
                        v.x = x0 * __cosf(f2.x) + r0 * __sinf(f2.x);
                        v.y = x1 * __cosf(f2.y) + r1 * __sinf(f2.y);
                        *(float2*)(out + (size_t)h * T * DH + (size_t)t * DH + l) = v;
                    }
                }
            }
        } else {
            // cols 32..63: passthrough
#pragma unroll
            for (int mt = 0; mt < 2; mt++) {
#pragma unroll
                for (int rh = 0; rh < 2; rh++) {
                    int t = by * 128 + wm * 32 + mt * 16 + gid + rh * 8;
#pragma unroll
                    for (int nt = 0; nt < 4; nt++) {
                        int col = 32 + nt * 8 + tig * 2;
                        float2 v = make_float2(acc[mt][nt][rh * 2], acc[mt][nt][rh * 2 + 1]);
                        *(float2*)(out + (size_t)h * T * DH + (size_t)t * DH + col) = v;
                    }
                }
            }
        }
    }
}

// ---------------------------------------------------------------------------
// Causal flash attention, tf32 tensor cores + ldmatrix.
// Block = (head, 64-query tile), 128 threads = 4 warps, each warp 16 q-rows.
// ---------------------------------------------------------------------------
__global__ __launch_bounds__(128) void attn_kernel(
    const float* __restrict__ Q, const float* __restrict__ Kg,
    const float* __restrict__ Vg, float* __restrict__ vals)
{
    extern __shared__ uint32_t sm[];
    uint32_t* Qs = sm;            // 64x64
    uint32_t* Ks = sm + 4096;
    uint32_t* Vs = sm + 8192;
    uint32_t* Ps = sm + 12288;

    const int tid = threadIdx.x;
    const int lane = tid & 31;
    const int w = tid >> 5;
    const int gid = lane >> 2;
    const int tig = lane & 3;
    const int qb = 63 - blockIdx.x;   // long tiles first
    const int h = blockIdx.y;

    // ldmatrix per-thread constants
    const int lsub = lane >> 3;
    const int lr = lane & 7;
    const int khA = lsub >> 1;
    const int khB = lsub & 1;

    const uint32_t qs_s = (uint32_t)__cvta_generic_to_shared(Qs);
    const uint32_t ks_s = (uint32_t)__cvta_generic_to_shared(Ks);
    const uint32_t ps_s = (uint32_t)__cvta_generic_to_shared(Ps);

    // A row (Q and P share this): row stride 64 words = 256B
    const int rowA = w * 16 + lr + ((lsub & 1) << 3);
    const uint32_t aQ = qs_s + rowA * 256;
    const uint32_t aP = ps_s + rowA * 256;
    // B rows per nt-pair
    const int rowBr = lr + ((lsub >> 1) << 3);
    uint32_t bK[4];
#pragma unroll
    for (int np = 0; np < 4; np++)
        bK[np] = ks_s + (np * 16 + rowBr) * 256;

    const float* Qh = Q + (size_t)h * T * DH;
    const float* Kh = Kg + (size_t)h * T * DH;
    const float* Vh = Vg + (size_t)h * T * DH;

    // Load Q tile, pre-scaled by 1/sqrt(DH)=0.125, tf32, swizzled
#pragma unroll
    for (int i = 0; i < 8; i++) {
        int f = tid + i * 128;
        int m = f >> 4, kg = f & 15;
        float4 v4 = *(const float4*)(Qh + (size_t)(qb * 64 + m) * DH + kg * 4);
        uint4 u = make_uint4(f2tf(v4.x * 0.125f), f2tf(v4.y * 0.125f),
                             f2tf(v4.z * 0.125f), f2tf(v4.w * 0.125f));
        *(uint4*)&Qs[m * 64 + ((kg ^ (m & 7)) << 2)] = u;
    }

    float o[8][4];
#pragma unroll
    for (int nt = 0; nt < 8; nt++)
#pragma unroll
        for (int r = 0; r < 4; r++) o[nt][r] = 0.f;
    float mr[2] = {-1e30f, -1e30f};
    float lr2[2] = {0.f, 0.f};

    const int r0 = w * 16 + gid;   // local q-row (first of pair)

    for (int jb = 0; jb <= qb; jb++) {
        __syncthreads();
#pragma unroll
        for (int i = 0; i < 8; i++) {
            int f = tid + i * 128;
            int m = f >> 4, kg = f & 15;
            float4 k4 = *(const float4*)(Kh + (size_t)(jb * 64 + m) * DH + kg * 4);
            uint4 uk = make_uint4(f2tf(k4.x), f2tf(k4.y), f2tf(k4.z), f2tf(k4.w));
            *(uint4*)&Ks[m * 64 + ((kg ^ (m & 7)) << 2)] = uk;
            float4 v4 = *(const float4*)(Vh + (size_t)(jb * 64 + m) * DH + kg * 4);
            uint4 uv = make_uint4(f2tf(v4.x), f2tf(v4.y), f2tf(v4.z), f2tf(v4.w));
            *(uint4*)&Vs[m * 64 + ((kg ^ (m & 7)) << 2)] = uv;
        }
        __syncthreads();

        // S = Q K^T  (16 x 64 per warp)
        float s[8][4];
#pragma unroll
        for (int nt = 0; nt < 8; nt++)
#pragma unroll
            for (int r = 0; r < 4; r++) s[nt][r] = 0.f;

#pragma unroll
        for (int ks = 0; ks < 8; ks++) {
            uint32_t a0, a1, a2, a3;
            ldsm4(a0, a1, a2, a3, aQ + (((2 * ks + khA) ^ lr) << 4));
#pragma unroll
            for (int np = 0; np < 4; np++) {
                uint32_t b00, b01, b10, b11;
                ldsm4(b00, b01, b10, b11, bK[np] + (((2 * ks + khB) ^ lr) << 4));
                mma_tf32(s[2 * np], a0, a1, a2, a3, b00, b01);
                mma_tf32(s[2 * np + 1], a0, a1, a2, a3, b10, b11);
            }
        }

        // causal mask on diagonal tile
        if (jb == qb) {
#pragma unroll
            for (int nt = 0; nt < 8; nt++)
#pragma unroll
                for (int r = 0; r < 4; r++) {
                    int col = nt * 8 + tig * 2 + (r & 1);
                    int row = w * 16 + gid + ((r & 2) ? 8 : 0);
                    if (col > row) s[nt][r] = -1e30f;
                }
        }

        // online softmax (two rows per thread)
#pragma unroll
        for (int half = 0; half < 2; half++) {
            float mx = -1e30f;
#pragma unroll
            for (int nt = 0; nt < 8; nt++) {
                mx = fmaxf(mx, s[nt][half * 2]);
                mx = fmaxf(mx, s[nt][half * 2 + 1]);
            }
            mx = fmaxf(mx, __shfl_xor_sync(0xffffffffu, mx, 1));
            mx = fmaxf(mx, __shfl_xor_sync(0xffffffffu, mx, 2));
            float mnew = fmaxf(mr[half], mx);
            float alpha = __expf(mr[half] - mnew);
            mr[half] = mnew;
            float rs = 0.f;
#pragma unroll
            for (int nt = 0; nt < 8; nt++) {
                float p0 = __expf(s[nt][half * 2] - mnew);
                float p1 = __expf(s[nt][half * 2 + 1] - mnew);
                s[nt][half * 2] = p0;
                s[nt][half * 2 + 1] = p1;
                rs += p0 + p1;
            }
            rs += __shfl_xor_sync(0xffffffffu, rs, 1);
            rs += __shfl_xor_sync(0xffffffffu, rs, 2);
            lr2[half] = lr2[half] * alpha + rs;
#pragma unroll
            for (int nt = 0; nt < 8; nt++) {
                o[nt][half * 2] *= alpha;
                o[nt][half * 2 + 1] *= alpha;
            }
        }

        // write P (tf32) to warp-private smem rows
#pragma unroll
        for (int nt = 0; nt < 8; nt++) {
            int col = nt * 8 + tig * 2;
            int ra_ = r0, rb_ = r0 + 8;
            uint2 p01 = make_uint2(f2tf(s[nt][0]), f2tf(s[nt][1]));
            *(uint2*)&Ps[ra_ * 64 + (col ^ ((ra_ & 7) << 2))] = p01;
            uint2 p23 = make_uint2(f2tf(s[nt][2]), f2tf(s[nt][3]));
            *(uint2*)&Ps[rb_ * 64 + (col ^ ((rb_ & 7) << 2))] = p23;
        }
        __syncwarp();

        // O += P V   (P via ldmatrix, V via scalar LDS: k-transposed access)
#pragma unroll
        for (int ks = 0; ks < 8; ks++) {
            int kb = ks * 8;
            uint32_t a0, a1, a2, a3;
            ldsm4(a0, a1, a2, a3, aP + (((2 * ks + khA) ^ lr) << 4));
#pragma unroll
            for (int nt = 0; nt < 8; nt++) {
                int kr0 = kb + tig, kr1 = kb + tig + 4;
                uint32_t b0 = Vs[kr0 * 64 + ((nt * 8 + gid) ^ ((kr0 & 7) << 2))];
                uint32_t b1 = Vs[kr1 * 64 + ((nt * 8 + gid) ^ ((kr1 & 7) << 2))];
                mma_tf32(o[nt], a0, a1, a2, a3, b0, b1);
            }
        }
    }

    // epilogue: normalize and store
    float inv0 = 1.f / lr2[0];
    float inv1 = 1.f / lr2[1];
    int t0 = qb * 64 + r0;
    int t1 = t0 + 8;
#pragma unroll
    for (int nt = 0; nt < 8; nt++) {
        int col = h * DH + nt * 8 + tig * 2;
        float2 v0 = make_float2(o[nt][0] * inv0, o[nt][1] * inv0);
        *(float2*)(vals + (size_t)t0 * D + col) = v0;
        float2 v1 = make_float2(o[nt][2] * inv1, o[nt][3] * inv1);
        *(float2*)(vals + (size_t)t1 * D + col) = v1;
    }
}

// ---------------------------------------------------------------------------
extern "C" void kernel_launch(void* const* d_in, const int* in_sizes, int n_in,
                              void* d_out, int out_size)
{
    const float* q     = (const float*)d_in[0];
    const float* k     = (const float*)d_in[1];
    const float* v     = (const float*)d_in[2];
    // d_in[3] = mask (causal tril, known statically — unused)
    const float* freqs = (const float*)d_in[4];
    const float* w_q   = (const float*)d_in[5];
    const float* w_k   = (const float*)d_in[6];
    const float* w_v   = (const float*)d_in[7];
    const float* w_o   = (const float*)d_in[8];
    float* out = (float*)d_out;

    float *Qh, *Kh, *Vh, *Vals;
    cudaGetSymbolAddress((void**)&Qh, g_Qh);
    cudaGetSymbolAddress((void**)&Kh, g_Kh);
    cudaGetSymbolAddress((void**)&Vh, g_Vh);
    cudaGetSymbolAddress((void**)&Vals, g_Vals);

    dim3 pgrid(D / 64, T / 128);  // (16, 32)
    proj_kernel<<<pgrid, 256>>>(q, w_q, freqs, Qh, 1);
    proj_kernel<<<pgrid, 256>>>(k, w_k, freqs, Kh, 1);
    proj_kernel<<<pgrid, 256>>>(v, w_v, freqs, Vh, 1);

    size_t smem = 4 * 64 * 64 * sizeof(uint32_t);  // 64 KB
    cudaFuncSetAttribute(attn_kernel,
                         cudaFuncAttributeMaxDynamicSharedMemorySize, (int)smem);
    attn_kernel<<<dim3(T / 64, H), 128, smem>>>(Qh, Kh, Vh, Vals);

    proj_kernel<<<pgrid, 256>>>(Vals, w_o, nullptr, out, 0);
}